// round 1
// baseline (speedup 1.0000x reference)
#include <cuda_runtime.h>

#define D       100
#define D4      25          // D/4 float4s per row
#define KCODES  512
#define TM      64          // points per block
#define TN      64          // codes per chunk
#define NCHUNK  (KCODES/TN) // 8
#define THREADS 256
#define MAXBLOCKS 4096

__device__ float g_partial[MAXBLOCKS];

// Dynamic smem layout (floats):
// xs   [100][64]  : 6400     x-tile, k-major
// es   [100][64]  : 6400     e-chunk, k-major
// xx   [64]       : 64       ||x||^2
// ee   [64]       : 64       ||e||^2 for chunk
// bidx [64] (int) : 64       best code per point
// red  [256]      : 256      loss reduction
#define SMEM_FLOATS (6400 + 6400 + 64 + 64 + 64 + 256)

__global__ void vq_kernel(const float* __restrict__ x,
                          const float* __restrict__ emb,
                          float* __restrict__ out)
{
    extern __shared__ float sm[];
    float* xs   = sm;
    float* es   = sm + 6400;
    float* xx   = sm + 12800;
    float* ee   = sm + 12864;
    int*   bidx = (int*)(sm + 12928);
    float* red  = sm + 12992;

    const int tid = threadIdx.x;
    const int pt0 = blockIdx.x * TM;

    // ---- load x tile, transpose to k-major: xs[k][pt] ----
    for (int idx = tid; idx < TM * D4; idx += THREADS) {
        int pt = idx & 63;           // idx % 64  -> conflict-free STS
        int k4 = idx >> 6;           // idx / 64
        float4 g = ((const float4*)x)[(size_t)(pt0 + pt) * D4 + k4];
        int kb = k4 * 4;
        xs[(kb + 0) * 64 + pt] = g.x;
        xs[(kb + 1) * 64 + pt] = g.y;
        xs[(kb + 2) * 64 + pt] = g.z;
        xs[(kb + 3) * 64 + pt] = g.w;
    }
    __syncthreads();

    // ---- ||x||^2 per point ----
    if (tid < TM) {
        float s = 0.0f;
        #pragma unroll 10
        for (int k = 0; k < D; k++) {
            float v = xs[k * 64 + tid];
            s = fmaf(v, v, s);
        }
        xx[tid] = s;
    }

    const int tx = tid & 15;   // code group  (4 codes)
    const int ty = tid >> 4;   // point group (4 points)

    float bd[4];
    int   bi[4];
    #pragma unroll
    for (int r = 0; r < 4; r++) { bd[r] = 3.4e38f; bi[r] = 0; }

    for (int ch = 0; ch < NCHUNK; ch++) {
        __syncthreads();   // previous chunk fully consumed; xx ready (1st iter)
        const int c0 = ch * TN;

        // load e chunk, k-major: es[k][c]
        for (int idx = tid; idx < TN * D4; idx += THREADS) {
            int c  = idx & 63;
            int k4 = idx >> 6;
            float4 g = ((const float4*)emb)[(size_t)(c0 + c) * D4 + k4];
            int kb = k4 * 4;
            es[(kb + 0) * 64 + c] = g.x;
            es[(kb + 1) * 64 + c] = g.y;
            es[(kb + 2) * 64 + c] = g.z;
            es[(kb + 3) * 64 + c] = g.w;
        }
        __syncthreads();

        if (tid < TN) {
            float s = 0.0f;
            #pragma unroll 10
            for (int k = 0; k < D; k++) {
                float v = es[k * 64 + tid];
                s = fmaf(v, v, s);
            }
            ee[tid] = s;
        }
        __syncthreads();

        // ---- 64x64 dot tile, 4x4 per thread ----
        float acc[4][4];
        #pragma unroll
        for (int r = 0; r < 4; r++)
            #pragma unroll
            for (int c = 0; c < 4; c++) acc[r][c] = 0.0f;

        #pragma unroll 10
        for (int k = 0; k < D; k++) {
            float4 xv = *(const float4*)&xs[k * 64 + ty * 4];
            float4 ev = *(const float4*)&es[k * 64 + tx * 4];
            float xr[4] = {xv.x, xv.y, xv.z, xv.w};
            float er[4] = {ev.x, ev.y, ev.z, ev.w};
            #pragma unroll
            for (int r = 0; r < 4; r++)
                #pragma unroll
                for (int c = 0; c < 4; c++)
                    acc[r][c] = fmaf(xr[r], er[c], acc[r][c]);
        }

        // ---- distances + running argmin (first-index tie-break) ----
        #pragma unroll
        for (int r = 0; r < 4; r++) {
            float xxv = xx[ty * 4 + r];
            #pragma unroll
            for (int c = 0; c < 4; c++) {
                int code = c0 + tx * 4 + c;            // ascending within thread
                float t = xxv + ee[tx * 4 + c];        // fp32 round (matches A+B)
                float d = t - 2.0f * acc[r][c];        // fp32 round (matches -2M)
                if (d < bd[r]) { bd[r] = d; bi[r] = code; }
            }
        }
    }

    // ---- reduce argmin across the 16 code-threads (same ty) ----
    #pragma unroll
    for (int off = 8; off > 0; off >>= 1) {
        #pragma unroll
        for (int r = 0; r < 4; r++) {
            float od = __shfl_down_sync(0xFFFFFFFFu, bd[r], off, 16);
            int   oi = __shfl_down_sync(0xFFFFFFFFu, bi[r], off, 16);
            if (od < bd[r] || (od == bd[r] && oi < bi[r])) {
                bd[r] = od; bi[r] = oi;
            }
        }
    }
    if (tx == 0) {
        #pragma unroll
        for (int r = 0; r < 4; r++) bidx[ty * 4 + r] = bi[r];
    }
    __syncthreads();

    // ---- phase 2: quantize, straight-through output, loss partial ----
    float lsum = 0.0f;
    for (int idx = tid; idx < TM * D4; idx += THREADS) {
        int pt = idx / D4;
        int k4 = idx % D4;
        int best = bidx[pt];
        size_t gx = (size_t)(pt0 + pt) * D4 + k4;
        float4 xg = ((const float4*)x)[gx];
        float4 eg = ((const float4*)emb)[(size_t)best * D4 + k4];
        float4 o;
        float dd;
        dd = eg.x - xg.x; o.x = xg.x + dd; lsum = fmaf(dd, dd, lsum);
        dd = eg.y - xg.y; o.y = xg.y + dd; lsum = fmaf(dd, dd, lsum);
        dd = eg.z - xg.z; o.z = xg.z + dd; lsum = fmaf(dd, dd, lsum);
        dd = eg.w - xg.w; o.w = xg.w + dd; lsum = fmaf(dd, dd, lsum);
        ((float4*)out)[gx] = o;
    }

    // deterministic block reduction
    red[tid] = lsum;
    __syncthreads();
    #pragma unroll
    for (int s = 128; s > 0; s >>= 1) {
        if (tid < s) red[tid] += red[tid + s];
        __syncthreads();
    }
    if (tid == 0) g_partial[blockIdx.x] = red[0];
}

__global__ void loss_kernel(float* __restrict__ out, int nblocks,
                            long long nelem, long long nq)
{
    __shared__ double dred[256];
    double s = 0.0;
    for (int i = threadIdx.x; i < nblocks; i += 256)
        s += (double)g_partial[i];
    dred[threadIdx.x] = s;
    __syncthreads();
    #pragma unroll
    for (int st = 128; st > 0; st >>= 1) {
        if (threadIdx.x < st) dred[threadIdx.x] += dred[threadIdx.x + st];
        __syncthreads();
    }
    if (threadIdx.x == 0) {
        double mean = dred[0] / (double)nelem;
        out[nq]     = (float)mean;          // quantization_loss
        out[nq + 1] = (float)(0.25 * mean); // commitment_loss
    }
}

extern "C" void kernel_launch(void* const* d_in, const int* in_sizes, int n_in,
                              void* d_out, int out_size)
{
    const float* x   = (const float*)d_in[0];   // [N, 100] flattened
    const float* emb = (const float*)d_in[1];   // [512, 100]
    float* out = (float*)d_out;

    long long nelem = in_sizes[0];              // 26214400
    int npts = (int)(nelem / D);                // 262144
    int nblocks = npts / TM;                    // 4096

    size_t smembytes = SMEM_FLOATS * sizeof(float);
    cudaFuncSetAttribute(vq_kernel,
                         cudaFuncAttributeMaxDynamicSharedMemorySize,
                         (int)smembytes);

    vq_kernel<<<nblocks, THREADS, smembytes>>>(x, emb, out);
    loss_kernel<<<1, 256>>>(out, nblocks, nelem, nelem);
}

// round 2
// speedup vs baseline: 1.8142x; 1.8142x over previous
#include <cuda_runtime.h>

#define D       100
#define D4      25          // D/4 float4s per row
#define KCODES  512
#define TM      128         // points per block
#define TN      64          // codes per chunk
#define NCHUNK  (KCODES/TN) // 8
#define THREADS 256
#define MAXBLOCKS 4096

__device__ float g_partial[MAXBLOCKS];

// Dynamic smem layout (floats):
// xs   [100][128] : 12800    x-tile, k-major
// es   [100][64]  : 6400     e-chunk, k-major
// xx   [128]      : 128      ||x||^2
// ee   [64]       : 64       ||e||^2 for chunk
// bidx [128](int) : 128      best code per point
// red  [256]      : 256      loss reduction
#define XS_OFF   0
#define ES_OFF   12800
#define XX_OFF   19200
#define EE_OFF   19328
#define BI_OFF   19392
#define RED_OFF  19520
#define SMEM_FLOATS (19520 + 256)

typedef unsigned long long u64;

__device__ __forceinline__ u64 ffma2(u64 a, u64 b, u64 c) {
    u64 d;
    asm("fma.rn.f32x2 %0, %1, %2, %3;" : "=l"(d) : "l"(a), "l"(b), "l"(c));
    return d;
}
__device__ __forceinline__ u64 pack2(float x, float y) {
    u64 d;
    asm("mov.b64 %0, {%1, %2};" : "=l"(d) : "f"(x), "f"(y));
    return d;
}
__device__ __forceinline__ void unpack2(u64 v, float& lo, float& hi) {
    asm("mov.b64 {%0, %1}, %2;" : "=f"(lo), "=f"(hi) : "l"(v));
}

__global__ void vq_kernel(const float* __restrict__ x,
                          const float* __restrict__ emb,
                          float* __restrict__ out)
{
    extern __shared__ float sm[];
    float* xs   = sm + XS_OFF;
    float* es   = sm + ES_OFF;
    float* xx   = sm + XX_OFF;
    float* ee   = sm + EE_OFF;
    int*   bidx = (int*)(sm + BI_OFF);
    float* red  = sm + RED_OFF;

    const int tid = threadIdx.x;
    const int pt0 = blockIdx.x * TM;

    // ---- load x tile, transpose to k-major: xs[k][pt] ----
    for (int idx = tid; idx < TM * D4; idx += THREADS) {
        int pt = idx & 127;          // conflict-free STS
        int k4 = idx >> 7;
        float4 g = ((const float4*)x)[(size_t)(pt0 + pt) * D4 + k4];
        int kb = k4 * 4;
        xs[(kb + 0) * TM + pt] = g.x;
        xs[(kb + 1) * TM + pt] = g.y;
        xs[(kb + 2) * TM + pt] = g.z;
        xs[(kb + 3) * TM + pt] = g.w;
    }
    __syncthreads();

    // ---- ||x||^2 per point ----
    if (tid < TM) {
        float s = 0.0f;
        #pragma unroll 10
        for (int k = 0; k < D; k++) {
            float v = xs[k * TM + tid];
            s = fmaf(v, v, s);
        }
        xx[tid] = s;
    }

    const int tx = tid & 15;   // code group  (4 codes)
    const int ty = tid >> 4;   // point group (8 points)

    float bd[8];
    int   bi[8];
    #pragma unroll
    for (int r = 0; r < 8; r++) { bd[r] = 3.4e38f; bi[r] = 0; }

    for (int ch = 0; ch < NCHUNK; ch++) {
        __syncthreads();   // previous chunk fully consumed; xx ready (1st iter)
        const int c0 = ch * TN;

        // load e chunk, k-major: es[k][c]
        for (int idx = tid; idx < TN * D4; idx += THREADS) {
            int c  = idx & 63;
            int k4 = idx >> 6;
            float4 g = ((const float4*)emb)[(size_t)(c0 + c) * D4 + k4];
            int kb = k4 * 4;
            es[(kb + 0) * TN + c] = g.x;
            es[(kb + 1) * TN + c] = g.y;
            es[(kb + 2) * TN + c] = g.z;
            es[(kb + 3) * TN + c] = g.w;
        }
        __syncthreads();

        if (tid < TN) {
            float s = 0.0f;
            #pragma unroll 10
            for (int k = 0; k < D; k++) {
                float v = es[k * TN + tid];
                s = fmaf(v, v, s);
            }
            ee[tid] = s;
        }
        __syncthreads();

        // ---- 128x64 dot tile: 8 points x 4 codes per thread, f32x2 packed ----
        u64 acc[4][4];
        #pragma unroll
        for (int rp = 0; rp < 4; rp++)
            #pragma unroll
            for (int c = 0; c < 4; c++) acc[rp][c] = 0ULL;

        #pragma unroll 5
        for (int k = 0; k < D; k++) {
            longlong2 xv0 = *(const longlong2*)&xs[k * TM + ty * 8];
            longlong2 xv1 = *(const longlong2*)&xs[k * TM + ty * 8 + 4];
            u64 xp[4] = { (u64)xv0.x, (u64)xv0.y, (u64)xv1.x, (u64)xv1.y };
            float4 evv = *(const float4*)&es[k * TN + tx * 4];
            u64 ep[4] = { pack2(evv.x, evv.x), pack2(evv.y, evv.y),
                          pack2(evv.z, evv.z), pack2(evv.w, evv.w) };
            #pragma unroll
            for (int rp = 0; rp < 4; rp++)
                #pragma unroll
                for (int c = 0; c < 4; c++)
                    acc[rp][c] = ffma2(xp[rp], ep[c], acc[rp][c]);
        }

        // ---- distances + running argmin (first-index tie-break) ----
        #pragma unroll
        for (int rp = 0; rp < 4; rp++) {
            float xx0 = xx[ty * 8 + rp * 2];
            float xx1 = xx[ty * 8 + rp * 2 + 1];
            #pragma unroll
            for (int c = 0; c < 4; c++) {
                int code = c0 + tx * 4 + c;            // ascending within thread
                float eev = ee[tx * 4 + c];
                float a0, a1;
                unpack2(acc[rp][c], a0, a1);
                float t0 = xx0 + eev;                  // fp32 round (matches A+B)
                float t1 = xx1 + eev;
                float d0 = t0 - 2.0f * a0;             // fp32 round (matches -2M)
                float d1 = t1 - 2.0f * a1;
                int r0 = rp * 2, r1 = rp * 2 + 1;
                if (d0 < bd[r0]) { bd[r0] = d0; bi[r0] = code; }
                if (d1 < bd[r1]) { bd[r1] = d1; bi[r1] = code; }
            }
        }
    }

    // ---- reduce argmin across the 16 code-threads (same ty) ----
    #pragma unroll
    for (int off = 8; off > 0; off >>= 1) {
        #pragma unroll
        for (int r = 0; r < 8; r++) {
            float od = __shfl_down_sync(0xFFFFFFFFu, bd[r], off, 16);
            int   oi = __shfl_down_sync(0xFFFFFFFFu, bi[r], off, 16);
            if (od < bd[r] || (od == bd[r] && oi < bi[r])) {
                bd[r] = od; bi[r] = oi;
            }
        }
    }
    if (tx == 0) {
        #pragma unroll
        for (int r = 0; r < 8; r++) bidx[ty * 8 + r] = bi[r];
    }
    __syncthreads();

    // ---- phase 2: quantize, straight-through output, loss partial ----
    float lsum = 0.0f;
    for (int idx = tid; idx < TM * D4; idx += THREADS) {
        int pt = idx / D4;
        int k4 = idx % D4;
        int best = bidx[pt];
        size_t gx = (size_t)(pt0 + pt) * D4 + k4;
        float4 xg = ((const float4*)x)[gx];
        float4 eg = ((const float4*)emb)[(size_t)best * D4 + k4];
        float4 o;
        float dd;
        dd = eg.x - xg.x; o.x = xg.x + dd; lsum = fmaf(dd, dd, lsum);
        dd = eg.y - xg.y; o.y = xg.y + dd; lsum = fmaf(dd, dd, lsum);
        dd = eg.z - xg.z; o.z = xg.z + dd; lsum = fmaf(dd, dd, lsum);
        dd = eg.w - xg.w; o.w = xg.w + dd; lsum = fmaf(dd, dd, lsum);
        ((float4*)out)[gx] = o;
    }

    // deterministic block reduction
    red[tid] = lsum;
    __syncthreads();
    #pragma unroll
    for (int s = 128; s > 0; s >>= 1) {
        if (tid < s) red[tid] += red[tid + s];
        __syncthreads();
    }
    if (tid == 0) g_partial[blockIdx.x] = red[0];
}

__global__ void loss_kernel(float* __restrict__ out, int nblocks,
                            long long nelem, long long nq)
{
    __shared__ double dred[256];
    double s = 0.0;
    for (int i = threadIdx.x; i < nblocks; i += 256)
        s += (double)g_partial[i];
    dred[threadIdx.x] = s;
    __syncthreads();
    #pragma unroll
    for (int st = 128; st > 0; st >>= 1) {
        if (threadIdx.x < st) dred[threadIdx.x] += dred[threadIdx.x + st];
        __syncthreads();
    }
    if (threadIdx.x == 0) {
        double mean = dred[0] / (double)nelem;
        out[nq]     = (float)mean;          // quantization_loss
        out[nq + 1] = (float)(0.25 * mean); // commitment_loss
    }
}

extern "C" void kernel_launch(void* const* d_in, const int* in_sizes, int n_in,
                              void* d_out, int out_size)
{
    const float* x   = (const float*)d_in[0];   // [N, 100] flattened
    const float* emb = (const float*)d_in[1];   // [512, 100]
    float* out = (float*)d_out;

    long long nelem = in_sizes[0];              // 26214400
    int npts = (int)(nelem / D);                // 262144
    int nblocks = npts / TM;                    // 2048

    size_t smembytes = SMEM_FLOATS * sizeof(float);
    cudaFuncSetAttribute(vq_kernel,
                         cudaFuncAttributeMaxDynamicSharedMemorySize,
                         (int)smembytes);

    vq_kernel<<<nblocks, THREADS, smembytes>>>(x, emb, out);
    loss_kernel<<<1, 256>>>(out, nblocks, nelem, nelem);
}